// round 1
// baseline (speedup 1.0000x reference)
#include <cuda_runtime.h>
#include <math.h>

// ---------------- problem constants ----------------
#define B2   2
#define ID32 32
#define SD   64
#define KSL  8        // num slots
#define N3   405224   // 74^3
#define D1   78       // conv1 out
#define D2   76       // conv2 out
#define D3   74       // conv3 out

// ---------------- device scratch ----------------
__device__ float g_buf1[2 * 32 * 78 * 78 * 78];   // conv1 out / conv3 out
__device__ float g_buf2[2 * 32 * 76 * 76 * 76];   // conv2 out
__device__ float g_k[2 * 64 * N3];                // k, layout [b][d][j]
__device__ float g_v[2 * 64 * N3];                // v, layout [b][d][j]
__device__ float g_slots[1024];
__device__ float g_q[1024];                       // [b][i][d], scale folded in
__device__ float g_upd[1024];                     // [b][i][d] numerator accumulators
__device__ float g_rowsum[16];                    // [b][i]

// =====================================================================
// Conv3d 3x3x3 VALID, Cout=32, relu.  Tile: 4(D) x 8(H) x 8(W), 256 thr.
// thread = (cout, h-row); owns 4x8 outputs, D handled in-thread so each
// smem row feeds up to 3 kd taps.
// =====================================================================
template <int CIN>
__global__ __launch_bounds__(256)
void conv3d_kernel(const float* __restrict__ in, const float* __restrict__ wg,
                   const float* __restrict__ bias, float* __restrict__ out,
                   int Di) {
    const int Do = Di - 2;
    const int tid = threadIdx.x;
    const int b  = blockIdx.z;
    const int nW = (Do + 7) >> 3;
    const int h0 = (blockIdx.x / nW) * 8;
    const int w0 = (blockIdx.x % nW) * 8;
    const int d0 = blockIdx.y * 4;

    extern __shared__ float smem[];
    float* ws    = smem;                 // CIN*27*32, layout [ci*27+t][cout]
    float* patch = smem + CIN * 27 * 32; // CIN*600 (>=8192 for out staging)

    // load + transpose weights
    const int WTOT = 32 * CIN * 27;
    for (int idx = tid; idx < WTOT; idx += 256) {
        int co = idx / (CIN * 27);
        int r  = idx - co * (CIN * 27);
        ws[r * 32 + co] = wg[idx];
    }
    // load input patch CIN x 6 x 10 x 10 (zero-fill OOB)
    for (int idx = tid; idx < CIN * 600; idx += 256) {
        int ci = idx / 600;
        int r  = idx - ci * 600;
        int dd = r / 100;  int r2 = r - dd * 100;
        int hh = r2 / 10;  int ww = r2 - hh * 10;
        int gd = d0 + dd, gh = h0 + hh, gw = w0 + ww;
        float val = 0.f;
        if (gd < Di && gh < Di && gw < Di)
            val = in[(((b * CIN + ci) * Di + gd) * Di + gh) * Di + gw];
        patch[idx] = val;
    }
    __syncthreads();

    const int cout = tid >> 3;
    const int hg   = tid & 7;
    const float bv = bias[cout];

    float acc[4][8];
#pragma unroll
    for (int i = 0; i < 4; i++)
#pragma unroll
        for (int j = 0; j < 8; j++) acc[i][j] = 0.f;

    for (int ci = 0; ci < CIN; ci++) {
        float wr[27];
#pragma unroll
        for (int t = 0; t < 27; t++) wr[t] = ws[(ci * 27 + t) * 32 + cout];
        const float* pbase = patch + ci * 600;
#pragma unroll
        for (int kh = 0; kh < 3; kh++) {
            const float* rowb = pbase + (hg + kh) * 10;
#pragma unroll
            for (int dd = 0; dd < 6; dd++) {
                float row[10];
                const float2* rp = (const float2*)(rowb + dd * 100);
#pragma unroll
                for (int j = 0; j < 5; j++) ((float2*)row)[j] = rp[j];
#pragma unroll
                for (int kd = 0; kd < 3; kd++) {
                    const int dlo = dd - kd;
                    if (dlo >= 0 && dlo < 4) {
#pragma unroll
                        for (int kw = 0; kw < 3; kw++) {
                            float wv = wr[kd * 9 + kh * 3 + kw];
#pragma unroll
                            for (int w = 0; w < 8; w++)
                                acc[dlo][w] += wv * row[w + kw];
                        }
                    }
                }
            }
        }
    }
    __syncthreads();   // done with patch
    // stage outputs (relu + bias) for coalesced store
#pragma unroll
    for (int dd = 0; dd < 4; dd++)
#pragma unroll
        for (int w = 0; w < 8; w++) {
            float v = acc[dd][w] + bv;
            patch[cout * 256 + dd * 64 + hg * 8 + w] = v > 0.f ? v : 0.f;
        }
    __syncthreads();
    const int DoDo = Do * Do;
    for (int idx = tid; idx < 8192; idx += 256) {
        int co = idx >> 8;
        int r  = idx & 255;
        int dd = r >> 6;
        int hh = (r >> 3) & 7;
        int w  = r & 7;
        int od = d0 + dd, oh = h0 + hh, ow = w0 + w;
        if (od < Do && oh < Do && ow < Do)
            out[((b * 32 + co) * Do + od) * DoDo + oh * Do + ow] = patch[idx];
    }
}

// =====================================================================
// feature LN + k/v projection. x: [b][c][j] (conv3 out), k/v out d-major.
// =====================================================================
__global__ __launch_bounds__(256)
void lnkv_kernel(const float* __restrict__ x, const float* __restrict__ lg,
                 const float* __restrict__ lb, const float* __restrict__ kw,
                 const float* __restrict__ vw) {
    __shared__ float kws[2048], vws[2048], gs[32], bs[32];
    const int tid = threadIdx.x;
    for (int i = tid; i < 2048; i += 256) { kws[i] = kw[i]; vws[i] = vw[i]; }
    if (tid < 32) { gs[tid] = lg[tid]; bs[tid] = lb[tid]; }
    __syncthreads();
    const int b = blockIdx.y;
    const int j = blockIdx.x * 256 + tid;
    if (j >= N3) return;
    float xv[32];
    float s = 0.f;
#pragma unroll
    for (int c = 0; c < 32; c++) { xv[c] = x[(b * 32 + c) * N3 + j]; s += xv[c]; }
    const float m = s * (1.f / 32.f);
    float vs = 0.f;
#pragma unroll
    for (int c = 0; c < 32; c++) { float d = xv[c] - m; vs += d * d; }
    const float inv = rsqrtf(vs * (1.f / 32.f) + 1e-5f);
#pragma unroll
    for (int c = 0; c < 32; c++) xv[c] = (xv[c] - m) * inv * gs[c] + bs[c];
#pragma unroll 4
    for (int d = 0; d < 64; d++) {
        const float4* k4 = (const float4*)(kws + d * 32);
        const float4* v4 = (const float4*)(vws + d * 32);
        float ka = 0.f, va = 0.f;
#pragma unroll
        for (int c4 = 0; c4 < 8; c4++) {
            float4 a = k4[c4], bq = v4[c4];
            int c = c4 * 4;
            ka += xv[c] * a.x + xv[c + 1] * a.y + xv[c + 2] * a.z + xv[c + 3] * a.w;
            va += xv[c] * bq.x + xv[c + 1] * bq.y + xv[c + 2] * bq.z + xv[c + 3] * bq.w;
        }
        g_k[(b * 64 + d) * N3 + j] = ka;
        g_v[(b * 64 + d) * N3 + j] = va;
    }
}

// =====================================================================
// q = LN(slots) @ q_w^T * SD^-0.5 ; also zeroes iteration accumulators.
// =====================================================================
__global__ __launch_bounds__(256)
void q_kernel(const float* __restrict__ slots, const float* __restrict__ lg,
              const float* __restrict__ lb, const float* __restrict__ qw) {
    __shared__ float s[1024], qws[4096], gs[64], bs[64], mm[16], iv[16];
    const int tid = threadIdx.x;
    for (int i = tid; i < 1024; i += 256) { s[i] = slots[i]; g_upd[i] = 0.f; }
    for (int i = tid; i < 4096; i += 256) qws[i] = qw[i];
    if (tid < 64) { gs[tid] = lg[tid]; bs[tid] = lb[tid]; }
    if (tid < 16) g_rowsum[tid] = 0.f;
    __syncthreads();
    if (tid < 16) {
        float sum = 0.f;
        for (int d = 0; d < 64; d++) sum += s[tid * 64 + d];
        float m = sum * (1.f / 64.f);
        float vs = 0.f;
        for (int d = 0; d < 64; d++) { float t = s[tid * 64 + d] - m; vs += t * t; }
        mm[tid] = m;
        iv[tid] = rsqrtf(vs * (1.f / 64.f) + 1e-5f);
    }
    __syncthreads();
    for (int k = 0; k < 4; k++) {
        int o = k * 256 + tid;
        int r = o >> 6, d = o & 63;
        float m = mm[r], inv = iv[r];
        float acc = 0.f;
#pragma unroll
        for (int c = 0; c < 64; c++)
            acc += ((s[r * 64 + c] - m) * inv * gs[c] + bs[c]) * qws[d * 64 + c];
        g_q[o] = acc * 0.125f;   // 64^-0.5
    }
}

// =====================================================================
// fused attention iteration: dots -> softmax over 8 slots -> (+eps)
// -> accumulate rowsum and Sum_j a*v  (normalization folded out).
// =====================================================================
__global__ __launch_bounds__(256)
void attn_kernel(float* __restrict__ attn_out) {
    extern __shared__ float sm[];
    float* qs = sm;             // 512
    float* as = sm + 512;       // 8 * 256
    float* vs = sm + 2560;      // 64 * 257 (padded)
    const int tid  = threadIdx.x;
    const int b    = blockIdx.y;
    const int dd   = tid & 63;
    const int ib   = tid >> 6;          // 0..3 ; pairs (ib,dd),(ib+4,dd)
    const int wid  = tid >> 5;
    const int lane = tid & 31;
    for (int i = tid; i < 512; i += 256) qs[i] = g_q[b * 512 + i];

    float acc0 = 0.f, acc1 = 0.f, rs = 0.f;
    const int nch = (N3 + 255) >> 8;
    for (int c = blockIdx.x; c < nch; c += gridDim.x) {
        const int j0 = c << 8;
        const int j  = j0 + tid;
        __syncthreads();
        // ---- phase 1: dots + softmax over slots ----
        float a[8];
        if (j < N3) {
            float dots[8];
#pragma unroll
            for (int i = 0; i < 8; i++) dots[i] = 0.f;
#pragma unroll 16
            for (int d = 0; d < 64; d++) {
                float kv = g_k[(b * 64 + d) * N3 + j];
#pragma unroll
                for (int i = 0; i < 8; i++) dots[i] += qs[i * 64 + d] * kv;
            }
            float mx = dots[0];
#pragma unroll
            for (int i = 1; i < 8; i++) mx = fmaxf(mx, dots[i]);
            float ssum = 0.f;
#pragma unroll
            for (int i = 0; i < 8; i++) { a[i] = expf(dots[i] - mx); ssum += a[i]; }
            const float rinv = 1.f / ssum;
#pragma unroll
            for (int i = 0; i < 8; i++) a[i] = a[i] * rinv + 1e-8f;
            if (attn_out) {
#pragma unroll
                for (int i = 0; i < 8; i++)
                    attn_out[(b * 8 + i) * N3 + j] = a[i];
            }
        } else {
#pragma unroll
            for (int i = 0; i < 8; i++) a[i] = 0.f;
        }
#pragma unroll
        for (int i = 0; i < 8; i++) as[i * 256 + tid] = a[i];
        // cooperative v chunk load
        for (int idx = tid; idx < 64 * 256; idx += 256) {
            int d  = idx >> 8, jj = idx & 255;
            int jg = j0 + jj;
            vs[d * 257 + jj] = (jg < N3) ? g_v[(b * 64 + d) * N3 + jg] : 0.f;
        }
        __syncthreads();
        // ---- rowsum: warp w reduces slot-row w ----
        {
            float p = 0.f;
#pragma unroll
            for (int k = 0; k < 8; k++) p += as[wid * 256 + lane + k * 32];
#pragma unroll
            for (int off = 16; off; off >>= 1) p += __shfl_xor_sync(0xffffffffu, p, off);
            rs += p;
        }
        // ---- phase 2: update GEMM chunk ----
        const float* ap0 = as + ib * 256;
        const float* ap1 = as + (ib + 4) * 256;
        const float* vp  = vs + dd * 257;
#pragma unroll 8
        for (int jj = 0; jj < 256; jj++) {
            float vv = vp[jj];
            acc0 += ap0[jj] * vv;
            acc1 += ap1[jj] * vv;
        }
    }
    atomicAdd(&g_upd[(b * 8 + ib) * 64 + dd], acc0);
    atomicAdd(&g_upd[(b * 8 + ib + 4) * 64 + dd], acc1);
    if (lane == 0) atomicAdd(&g_rowsum[b * 8 + wid], rs);
}

// =====================================================================
// GRU cell + LN + MLP residual over the 16 slot rows. One block.
// =====================================================================
__global__ __launch_bounds__(512)
void gru_kernel(const float* __restrict__ slots_prev,
                const float* __restrict__ wih, const float* __restrict__ whh,
                const float* __restrict__ bih, const float* __restrict__ bhh,
                const float* __restrict__ lng, const float* __restrict__ lnb,
                const float* __restrict__ w1, const float* __restrict__ rb1,
                const float* __restrict__ w2, const float* __restrict__ rb2,
                float* __restrict__ slots_final) {
    __shared__ float S[9216];
    float* u  = S;           // 1024
    float* h  = S + 1024;    // 1024
    float* xg = S + 2048;    // 3072
    float* hg = S + 5120;    // 3072
    float* nh = S + 8192;    // 1024
    float* normed = S + 2048;  // reuse xg
    float* t1     = S + 5120;  // reuse hg
    const int tid = threadIdx.x;

    for (int k = 0; k < 2; k++) {
        int idx = k * 512 + tid;
        int r = idx >> 6;
        u[idx] = g_upd[idx] / g_rowsum[r];
        h[idx] = slots_prev[idx];
    }
    __syncthreads();
    for (int k = 0; k < 6; k++) {
        int p = k * 512 + tid;
        int r = p / 192, c = p - r * 192;
        float xa = bih[c], ha = bhh[c];
        const float* wr = wih + c * 64;
        const float* hr = whh + c * 64;
#pragma unroll 16
        for (int d = 0; d < 64; d++) {
            xa += u[r * 64 + d] * wr[d];
            ha += h[r * 64 + d] * hr[d];
        }
        xg[p] = xa; hg[p] = ha;
    }
    __syncthreads();
    for (int k = 0; k < 2; k++) {
        int idx = k * 512 + tid;
        int r = idx >> 6, d = idx & 63;
        float rg = 1.f / (1.f + expf(-(xg[r * 192 + d] + hg[r * 192 + d])));
        float z  = 1.f / (1.f + expf(-(xg[r * 192 + 64 + d] + hg[r * 192 + 64 + d])));
        float n  = tanhf(xg[r * 192 + 128 + d] + rg * hg[r * 192 + 128 + d]);
        nh[idx] = (1.f - z) * n + z * h[idx];
    }
    __syncthreads();
    {   // LN per row, warp w <-> row w
        const int w = tid >> 5, lane = tid & 31;
        float e0 = nh[w * 64 + lane], e1 = nh[w * 64 + 32 + lane];
        float s = e0 + e1;
#pragma unroll
        for (int off = 16; off; off >>= 1) s += __shfl_xor_sync(0xffffffffu, s, off);
        float m = s * (1.f / 64.f);
        float d0 = e0 - m, d1 = e1 - m;
        float vq = d0 * d0 + d1 * d1;
#pragma unroll
        for (int off = 16; off; off >>= 1) vq += __shfl_xor_sync(0xffffffffu, vq, off);
        float inv = rsqrtf(vq * (1.f / 64.f) + 1e-5f);
        normed[w * 64 + lane]      = d0 * inv * lng[lane] + lnb[lane];
        normed[w * 64 + 32 + lane] = d1 * inv * lng[32 + lane] + lnb[32 + lane];
    }
    __syncthreads();
    for (int k = 0; k < 4; k++) {
        int p = k * 512 + tid;
        int r = p >> 7, c = p & 127;
        float acc = rb1[c];
        const float* wr = w1 + c * 64;
#pragma unroll 16
        for (int d = 0; d < 64; d++) acc += normed[r * 64 + d] * wr[d];
        t1[p] = fmaxf(acc, 0.f);
    }
    __syncthreads();
    for (int k = 0; k < 2; k++) {
        int idx = k * 512 + tid;
        int r = idx >> 6, d = idx & 63;
        float acc = rb2[d];
        const float* wr = w2 + d * 128;
#pragma unroll 16
        for (int c = 0; c < 128; c++) acc += t1[r * 128 + c] * wr[c];
        float val = nh[idx] + acc;
        g_slots[idx] = val;
        if (slots_final) slots_final[idx] = val;
    }
}

// =====================================================================
// host driver
// =====================================================================
extern "C" void kernel_launch(void* const* d_in, const int* in_sizes, int n_in,
                              void* d_out, int out_size) {
    (void)in_sizes; (void)n_in; (void)out_size;
    const float* p_slots = (const float*)d_in[0];
    const float* p_oin   = (const float*)d_in[1];
    const float* w1  = (const float*)d_in[2];
    const float* b1  = (const float*)d_in[3];
    const float* w2  = (const float*)d_in[4];
    const float* b2  = (const float*)d_in[5];
    const float* w3  = (const float*)d_in[6];
    const float* b3  = (const float*)d_in[7];
    const float* kw  = (const float*)d_in[8];
    const float* vw  = (const float*)d_in[9];
    const float* qlg = (const float*)d_in[10];
    const float* qlb = (const float*)d_in[11];
    const float* qw  = (const float*)d_in[12];
    const float* gwih = (const float*)d_in[13];
    const float* gwhh = (const float*)d_in[14];
    const float* gbih = (const float*)d_in[15];
    const float* gbhh = (const float*)d_in[16];
    const float* rlg = (const float*)d_in[17];
    const float* rlb = (const float*)d_in[18];
    const float* rw1 = (const float*)d_in[19];
    const float* rb1 = (const float*)d_in[20];
    const float* rw2 = (const float*)d_in[21];
    const float* rb2 = (const float*)d_in[22];
    const float* flg = (const float*)d_in[23];
    const float* flb = (const float*)d_in[24];
    float* out = (float*)d_out;

    const size_t smem32 = (size_t)(32 * 27 * 32 + 32 * 600) * sizeof(float);
    const size_t smem4  = (size_t)(4 * 27 * 32 + 8192) * sizeof(float);
    const size_t smemA  = (size_t)(512 + 2048 + 64 * 257) * sizeof(float);
    cudaFuncSetAttribute(conv3d_kernel<32>, cudaFuncAttributeMaxDynamicSharedMemorySize, (int)smem32);
    cudaFuncSetAttribute(conv3d_kernel<4>,  cudaFuncAttributeMaxDynamicSharedMemorySize, (int)smem4);
    cudaFuncSetAttribute(attn_kernel,       cudaFuncAttributeMaxDynamicSharedMemorySize, (int)smemA);

    float *buf1, *buf2, *slots_g;
    cudaGetSymbolAddress((void**)&buf1, g_buf1);
    cudaGetSymbolAddress((void**)&buf2, g_buf2);
    cudaGetSymbolAddress((void**)&slots_g, g_slots);

    // conv1: 80 -> 78
    conv3d_kernel<4><<<dim3(10 * 10, 20, 2), 256, smem4>>>(p_oin, w1, b1, buf1, 80);
    // conv2: 78 -> 76
    conv3d_kernel<32><<<dim3(10 * 10, 19, 2), 256, smem32>>>(buf1, w2, b2, buf2, 78);
    // conv3: 76 -> 74 (into buf1)
    conv3d_kernel<32><<<dim3(10 * 10, 19, 2), 256, smem32>>>(buf2, w3, b3, buf1, 76);
    // feature LN + k/v projection
    lnkv_kernel<<<dim3((N3 + 255) / 256, 2), 256>>>(buf1, flg, flb, kw, vw);

    for (int it = 0; it < 3; it++) {
        const float* sp = (it == 0) ? p_slots : slots_g;
        q_kernel<<<1, 256>>>(sp, qlg, qlb, qw);
        attn_kernel<<<dim3(222, 2), 256, smemA>>>((it == 2) ? (out + 1024) : (float*)0);
        gru_kernel<<<1, 512>>>(sp, gwih, gwhh, gbih, gbhh, rlg, rlb,
                               rw1, rb1, rw2, rb2, (it == 2) ? out : (float*)0);
    }
}